// round 14
// baseline (speedup 1.0000x reference)
#include <cuda_runtime.h>
#include <cuda_bf16.h>
#include <cstdint>

#define D_MODEL 1024
#define N_HEADS 16
#define DKH     64
#define B_      4
#define T_      2048
#define M_TOT   (B_ * T_)        // 8192
#define N_QKV   (3 * D_MODEL)    // 3072
#define GK      1024

// ---------------- scratch (device globals; no allocation allowed) ----------
__device__ __nv_bfloat16 g_xh[(size_t)M_TOT * GK];      // x        [M,K]
__device__ __nv_bfloat16 g_xl[(size_t)M_TOT * GK];
__device__ __nv_bfloat16 g_wqh[(size_t)N_QKV * GK];     // w_qkv^T  [N,K]
__device__ __nv_bfloat16 g_wql[(size_t)N_QKV * GK];
__device__ __nv_bfloat16 g_woh[(size_t)D_MODEL * GK];   // w_out^T  [N,K]
__device__ __nv_bfloat16 g_wol[(size_t)D_MODEL * GK];
__device__ __nv_bfloat16 g_ah[(size_t)M_TOT * GK];      // attn out [M,K]
__device__ __nv_bfloat16 g_al[(size_t)M_TOT * GK];
__device__ __nv_bfloat16 g_qh[(size_t)64 * T_ * DKH];   // [bh][t][dk], pre-scaled
__device__ __nv_bfloat16 g_ql[(size_t)64 * T_ * DKH];
__device__ __nv_bfloat16 g_kh[(size_t)64 * T_ * DKH];
__device__ __nv_bfloat16 g_kl[(size_t)64 * T_ * DKH];
__device__ __nv_bfloat16 g_vh[(size_t)64 * DKH * T_];   // V^T [bh][dk][t]
__device__ __nv_bfloat16 g_vl[(size_t)64 * DKH * T_];

// ============================ helpers ======================================
#define MMA_BF16(D, A, b0, b1) \
    asm volatile("mma.sync.aligned.m16n8k16.row.col.f32.bf16.bf16.f32 " \
        "{%0,%1,%2,%3}, {%4,%5,%6,%7}, {%8,%9}, {%0,%1,%2,%3};" \
        : "+f"((D)[0]), "+f"((D)[1]), "+f"((D)[2]), "+f"((D)[3]) \
        : "r"((A)[0]), "r"((A)[1]), "r"((A)[2]), "r"((A)[3]), "r"(b0), "r"(b1))

__device__ __forceinline__ uint32_t smem_u32(const void* p) {
    uint32_t a;
    asm("{ .reg .u64 t; cvta.to.shared.u64 t, %1; cvt.u32.u64 %0, t; }"
        : "=r"(a) : "l"(p));
    return a;
}
#define CP16(dst, src) \
    asm volatile("cp.async.cg.shared.global [%0], [%1], 16;" \
                 :: "r"((uint32_t)(dst)), "l"(src) : "memory")
#define CP_COMMIT() asm volatile("cp.async.commit_group;" ::: "memory")
#define CP_WAIT1()  asm volatile("cp.async.wait_group 1;" ::: "memory")

__device__ __forceinline__ void bf16_split(float x, unsigned short& h, unsigned short& l)
{
    __nv_bfloat16 hb = __float2bfloat16(x);
    h = __bfloat16_as_ushort(hb);
    l = __bfloat16_as_ushort(__float2bfloat16(x - __bfloat162float(hb)));
}
__device__ __forceinline__ void split2(float a, float b, uint32_t& hi, uint32_t& lo)
{
    unsigned short ha, la, hb, lb;
    bf16_split(a, ha, la);
    bf16_split(b, hb, lb);
    hi = (uint32_t)ha | ((uint32_t)hb << 16);
    lo = (uint32_t)la | ((uint32_t)lb << 16);
}

// ===================== convert / split kernels =============================
__global__ __launch_bounds__(256)
void cvt_split(const float* __restrict__ in, int n4)
{
    int i = blockIdx.x * 256 + threadIdx.x;
    if (i >= n4) return;
    float4 v = ((const float4*)in)[i];
    uint32_t h0, l0, h1, l1;
    split2(v.x, v.y, h0, l0);
    split2(v.z, v.w, h1, l1);
    ((uint2*)g_xh)[i] = make_uint2(h0, h1);
    ((uint2*)g_xl)[i] = make_uint2(l0, l1);
}

template<int W>
__global__ __launch_bounds__(256)
void cvt_split_T(const float* __restrict__ in, int N)
{
    __shared__ float t[32][33];
    int n0 = blockIdx.x * 32, k0 = blockIdx.y * 32;
    int tx = threadIdx.x, ty = threadIdx.y;   // 32 x 8
    #pragma unroll
    for (int i = 0; i < 4; i++) {
        int k = ty + i * 8;
        t[k][tx] = in[(size_t)(k0 + k) * N + n0 + tx];
    }
    __syncthreads();
    __nv_bfloat16* oh = (W == 0) ? g_wqh : g_woh;
    __nv_bfloat16* ol = (W == 0) ? g_wql : g_wol;
    #pragma unroll
    for (int i = 0; i < 4; i++) {
        int n = ty + i * 8;
        float x = t[tx][n];
        unsigned short hh, ll;
        bf16_split(x, hh, ll);
        size_t o = (size_t)(n0 + n) * GK + k0 + tx;
        oh[o] = __ushort_as_bfloat16(hh);
        ol[o] = __ushort_as_bfloat16(ll);
    }
}

// ===================== 3-stage cp.async bf16 HMMA GEMM =====================
// Pre-split operands: A [M,K] hi/lo, B [N,K] hi/lo. C = AhBh + AhBl + AlBh.
// CTA 128x128, 8 warps 2x4, warp 64x32, BK=16, 3-stage cp.async pipeline.
#define BKS   16
#define NST   (GK / BKS)
#define AST   24                      // smem row stride (bf16)
#define TILE_BYTES (128 * AST * 2)    // 6144 B per hi-or-lo tile
#define STAGE_BYTES (4 * TILE_BYTES)  // Ah,Al,Bh,Bl = 24576 B
#define GEMM_SMEM (3 * STAGE_BYTES)   // 73728 B

template<int MODE>
__global__ __launch_bounds__(256)
void gemm_mma(float* __restrict__ Cp, int N)
{
    extern __shared__ __align__(16) char smem[];

    const int tid  = threadIdx.x;
    const int wid  = tid >> 5;
    const int lane = tid & 31;
    const int wm   = wid & 1;
    const int wn   = wid >> 1;
    const int gid  = lane >> 2;
    const int tig  = lane & 3;
    const int row0 = blockIdx.y * 128;
    const int col0 = blockIdx.x * 128;

    const __nv_bfloat16* Ah_g = (MODE == 0) ? g_xh : g_ah;
    const __nv_bfloat16* Al_g = (MODE == 0) ? g_xl : g_al;
    const __nv_bfloat16* Bh_g = (MODE == 0) ? g_wqh : g_woh;
    const __nv_bfloat16* Bl_g = (MODE == 0) ? g_wql : g_wol;

    float d[4][4][4];
    #pragma unroll
    for (int i = 0; i < 4; i++)
        #pragma unroll
        for (int j = 0; j < 4; j++)
            #pragma unroll
            for (int e = 0; e < 4; e++) d[i][j][e] = 0.f;

    // copy slot: row r8 (0..127), 8-elem chunk co (0 or 8)
    const int r8 = tid >> 1, co = (tid & 1) * 8;
    const uint32_t sbase = smem_u32(smem);
    const uint32_t my_sts = sbase + (uint32_t)(r8 * AST + co) * 2;

    // issue one stage's cp.asyncs into buffer b
    auto issue = [&](int kt, int b) {
        const size_t gofs_a = (size_t)(row0 + r8) * GK + kt * BKS + co;
        const size_t gofs_b = (size_t)(col0 + r8) * GK + kt * BKS + co;
        const uint32_t st = my_sts + b * STAGE_BYTES;
        CP16(st,                  Ah_g + gofs_a);
        CP16(st + TILE_BYTES,     Al_g + gofs_a);
        CP16(st + 2 * TILE_BYTES, Bh_g + gofs_b);
        CP16(st + 3 * TILE_BYTES, Bl_g + gofs_b);
        CP_COMMIT();
    };

    issue(0, 0);
    issue(1, 1);

    const int kb = tig * 2;
    int buf = 0;
    for (int kt = 0; kt < NST; kt++) {
        CP_WAIT1();          // stage kt resident
        __syncthreads();

        const __nv_bfloat16* sAh = (const __nv_bfloat16*)(smem + buf * STAGE_BYTES);
        const __nv_bfloat16* sAl = (const __nv_bfloat16*)(smem + buf * STAGE_BYTES + TILE_BYTES);
        const __nv_bfloat16* sBh = (const __nv_bfloat16*)(smem + buf * STAGE_BYTES + 2 * TILE_BYTES);
        const __nv_bfloat16* sBl = (const __nv_bfloat16*)(smem + buf * STAGE_BYTES + 3 * TILE_BYTES);

        uint32_t Ah[4][4], Al[4][4];
        #pragma unroll
        for (int mi = 0; mi < 4; mi++) {
            const int r0 = wm * 64 + mi * 16 + gid;
            Ah[mi][0] = *(const uint32_t*)&sAh[r0 * AST + kb];
            Ah[mi][1] = *(const uint32_t*)&sAh[(r0 + 8) * AST + kb];
            Ah[mi][2] = *(const uint32_t*)&sAh[r0 * AST + kb + 8];
            Ah[mi][3] = *(const uint32_t*)&sAh[(r0 + 8) * AST + kb + 8];
            Al[mi][0] = *(const uint32_t*)&sAl[r0 * AST + kb];
            Al[mi][1] = *(const uint32_t*)&sAl[(r0 + 8) * AST + kb];
            Al[mi][2] = *(const uint32_t*)&sAl[r0 * AST + kb + 8];
            Al[mi][3] = *(const uint32_t*)&sAl[(r0 + 8) * AST + kb + 8];
        }
        uint32_t Bh[4][2], Bl[4][2];
        #pragma unroll
        for (int ng = 0; ng < 4; ng++) {
            const int nr = wn * 32 + ng * 8 + gid;
            Bh[ng][0] = *(const uint32_t*)&sBh[nr * AST + kb];
            Bh[ng][1] = *(const uint32_t*)&sBh[nr * AST + kb + 8];
            Bl[ng][0] = *(const uint32_t*)&sBl[nr * AST + kb];
            Bl[ng][1] = *(const uint32_t*)&sBl[nr * AST + kb + 8];
        }
        #pragma unroll
        for (int mi = 0; mi < 4; mi++)
            #pragma unroll
            for (int ng = 0; ng < 4; ng++) {
                MMA_BF16(d[mi][ng], Ah[mi], Bh[ng][0], Bh[ng][1]);
                MMA_BF16(d[mi][ng], Ah[mi], Bl[ng][0], Bl[ng][1]);
                MMA_BF16(d[mi][ng], Al[mi], Bh[ng][0], Bh[ng][1]);
            }

        if (kt + 2 < NST)
            issue(kt + 2, (buf + 2) % 3);
        buf = (buf + 1) % 3;
    }

    // ---------------- epilogue (R13-proven) ----------------
    #pragma unroll
    for (int mi = 0; mi < 4; mi++)
        #pragma unroll
        for (int ng = 0; ng < 4; ng++) {
            const int n = col0 + wn * 32 + ng * 8 + tig * 2;
            #pragma unroll
            for (int h = 0; h < 2; h++) {
                const int m = row0 + wm * 64 + mi * 16 + gid + h * 8;
                float2 v;
                v.x = d[mi][ng][h * 2 + 0];
                v.y = d[mi][ng][h * 2 + 1];
                if (MODE == 0) {
                    const int b = m >> 11, t = m & (T_ - 1);
                    const int sidx = n >> 10;
                    const int dmi  = n & (D_MODEL - 1);
                    const int hh = dmi >> 6, dk = dmi & (DKH - 1);
                    const int bh = (b << 4) + hh;
                    if (sidx == 0) {
                        uint32_t hi, lo;
                        split2(0.125f * v.x, 0.125f * v.y, hi, lo);
                        const size_t idx = ((size_t)bh * T_ + t) * DKH + dk;
                        *(uint32_t*)&g_qh[idx] = hi;
                        *(uint32_t*)&g_ql[idx] = lo;
                    } else if (sidx == 1) {
                        uint32_t hi, lo;
                        split2(v.x, v.y, hi, lo);
                        const size_t idx = ((size_t)bh * T_ + t) * DKH + dk;
                        *(uint32_t*)&g_kh[idx] = hi;
                        *(uint32_t*)&g_kl[idx] = lo;
                    } else {
                        unsigned short h0, l0, h1, l1;
                        bf16_split(v.x, h0, l0);
                        bf16_split(v.y, h1, l1);
                        const size_t i0 = ((size_t)bh * DKH + dk) * T_ + t;
                        g_vh[i0] = __ushort_as_bfloat16(h0);
                        g_vl[i0] = __ushort_as_bfloat16(l0);
                        g_vh[i0 + T_] = __ushort_as_bfloat16(h1);
                        g_vl[i0 + T_] = __ushort_as_bfloat16(l1);
                    }
                } else {
                    *(float2*)(Cp + (size_t)m * N + n) = v;
                }
            }
        }
}

// ===================== bf16 HMMA causal flash attention (R13, proven) ======
#define VST 72

__global__ __launch_bounds__(256, 2)
void attn_mma()
{
    __shared__ __align__(16) __nv_bfloat16 sKh[64][VST], sKl[64][VST];
    __shared__ __align__(16) __nv_bfloat16 sVh[64][VST], sVl[64][VST];

    const int bh  = blockIdx.y;
    const int q0  = blockIdx.x * 128;
    const int tid = threadIdx.x;
    const int wid = tid >> 5;
    const int lane = tid & 31;
    const int gid = lane >> 2;
    const int tig = lane & 3;

    const __nv_bfloat16* Qh_g = g_qh + ((size_t)bh * T_ + q0) * DKH;
    const __nv_bfloat16* Ql_g = g_ql + ((size_t)bh * T_ + q0) * DKH;
    const __nv_bfloat16* Kh_g = g_kh + (size_t)bh * T_ * DKH;
    const __nv_bfloat16* Kl_g = g_kl + (size_t)bh * T_ * DKH;
    const __nv_bfloat16* Vh_g = g_vh + (size_t)bh * DKH * T_;
    const __nv_bfloat16* Vl_g = g_vl + (size_t)bh * DKH * T_;
    const float LOG2E = 1.4426950408889634f;

    uint32_t Qh[4][4], Ql[4][4];
    #pragma unroll
    for (int pass = 0; pass < 2; pass++) {
        #pragma unroll
        for (int i = 0; i < 2; i++) {
            const int c = tid + i * 256;
            const int rr = c >> 3, cc = (c & 7) * 8;
            *(uint4*)&sKh[rr][cc] = *(const uint4*)(Qh_g + (size_t)(pass * 64 + rr) * DKH + cc);
            *(uint4*)&sKl[rr][cc] = *(const uint4*)(Ql_g + (size_t)(pass * 64 + rr) * DKH + cc);
        }
        __syncthreads();
        if ((wid >> 2) == pass) {
            const int rb = (wid & 3) * 16 + gid;
            #pragma unroll
            for (int ks = 0; ks < 4; ks++) {
                const int kb = ks * 16 + tig * 2;
                Qh[ks][0] = *(const uint32_t*)&sKh[rb][kb];
                Qh[ks][1] = *(const uint32_t*)&sKh[rb + 8][kb];
                Qh[ks][2] = *(const uint32_t*)&sKh[rb][kb + 8];
                Qh[ks][3] = *(const uint32_t*)&sKh[rb + 8][kb + 8];
                Ql[ks][0] = *(const uint32_t*)&sKl[rb][kb];
                Ql[ks][1] = *(const uint32_t*)&sKl[rb + 8][kb];
                Ql[ks][2] = *(const uint32_t*)&sKl[rb][kb + 8];
                Ql[ks][3] = *(const uint32_t*)&sKl[rb + 8][kb + 8];
            }
        }
        __syncthreads();
    }

    float O[8][4];
    #pragma unroll
    for (int i = 0; i < 8; i++)
        #pragma unroll
        for (int e = 0; e < 4; e++) O[i][e] = 0.f;
    float mr[2] = {-1e30f, -1e30f}, lr[2] = {0.f, 0.f};

    const int qA = q0 + wid * 16 + gid;
    const int ntiles = (q0 >> 6) + 2;

    for (int t = 0; t < ntiles; t++) {
        const int k0 = t * 64;
        uint4 kh[2], kl[2], vh[2], vl[2];
        #pragma unroll
        for (int i = 0; i < 2; i++) {
            const int c = tid + i * 256;
            const int rr = c >> 3, cc = (c & 7) * 8;
            kh[i] = *(const uint4*)(Kh_g + (size_t)(k0 + rr) * DKH + cc);
            kl[i] = *(const uint4*)(Kl_g + (size_t)(k0 + rr) * DKH + cc);
            vh[i] = *(const uint4*)(Vh_g + (size_t)rr * T_ + k0 + cc);
            vl[i] = *(const uint4*)(Vl_g + (size_t)rr * T_ + k0 + cc);
        }
        __syncthreads();
        #pragma unroll
        for (int i = 0; i < 2; i++) {
            const int c = tid + i * 256;
            const int rr = c >> 3, cc = (c & 7) * 8;
            *(uint4*)&sKh[rr][cc] = kh[i];
            *(uint4*)&sKl[rr][cc] = kl[i];
            *(uint4*)&sVh[rr][cc] = vh[i];
            *(uint4*)&sVl[rr][cc] = vl[i];
        }
        __syncthreads();

        if (k0 <= q0 + wid * 16 + 15) {
            float S[8][4];
            #pragma unroll
            for (int i = 0; i < 8; i++)
                #pragma unroll
                for (int e = 0; e < 4; e++) S[i][e] = 0.f;
            #pragma unroll
            for (int ks = 0; ks < 4; ks++) {
                const int kb = ks * 16 + tig * 2;
                #pragma unroll
                for (int ng = 0; ng < 8; ng++) {
                    const int nr = ng * 8 + gid;
                    uint32_t bh0 = *(const uint32_t*)&sKh[nr][kb];
                    uint32_t bh1 = *(const uint32_t*)&sKh[nr][kb + 8];
                    uint32_t bl0 = *(const uint32_t*)&sKl[nr][kb];
                    uint32_t bl1 = *(const uint32_t*)&sKl[nr][kb + 8];
                    MMA_BF16(S[ng], Qh[ks], bh0, bh1);
                    MMA_BF16(S[ng], Qh[ks], bl0, bl1);
                    MMA_BF16(S[ng], Ql[ks], bh0, bh1);
                }
            }
            if (k0 + 63 > q0 + wid * 16) {
                #pragma unroll
                for (int ng = 0; ng < 8; ng++)
                    #pragma unroll
                    for (int e = 0; e < 4; e++) {
                        const int key = k0 + ng * 8 + tig * 2 + (e & 1);
                        const int q   = qA + (e >> 1) * 8;
                        if (key > q) S[ng][e] = -1e30f;
                    }
            }
            #pragma unroll
            for (int h = 0; h < 2; h++) {
                float mt = -1e30f;
                #pragma unroll
                for (int ng = 0; ng < 8; ng++)
                    mt = fmaxf(mt, fmaxf(S[ng][2 * h], S[ng][2 * h + 1]));
                mt = fmaxf(mt, __shfl_xor_sync(0xffffffff, mt, 1));
                mt = fmaxf(mt, __shfl_xor_sync(0xffffffff, mt, 2));
                const float mn = fmaxf(mr[h], mt);
                const float alpha = exp2f((mr[h] - mn) * LOG2E);
                float rs = 0.f;
                #pragma unroll
                for (int ng = 0; ng < 8; ng++) {
                    float p0 = exp2f((S[ng][2 * h] - mn) * LOG2E);
                    float p1 = exp2f((S[ng][2 * h + 1] - mn) * LOG2E);
                    S[ng][2 * h] = p0;
                    S[ng][2 * h + 1] = p1;
                    rs += p0 + p1;
                }
                rs += __shfl_xor_sync(0xffffffff, rs, 1);
                rs += __shfl_xor_sync(0xffffffff, rs, 2);
                lr[h] = lr[h] * alpha + rs;
                mr[h] = mn;
                #pragma unroll
                for (int ng = 0; ng < 8; ng++) {
                    O[ng][2 * h] *= alpha;
                    O[ng][2 * h + 1] *= alpha;
                }
            }
            #pragma unroll
            for (int ks = 0; ks < 4; ks++) {
                uint32_t Ph[4], Pl[4];
                split2(S[2 * ks][0],     S[2 * ks][1],     Ph[0], Pl[0]);
                split2(S[2 * ks][2],     S[2 * ks][3],     Ph[1], Pl[1]);
                split2(S[2 * ks + 1][0], S[2 * ks + 1][1], Ph[2], Pl[2]);
                split2(S[2 * ks + 1][2], S[2 * ks + 1][3], Ph[3], Pl[3]);
                const int kb = ks * 16 + tig * 2;
                #pragma unroll
                for (int ng = 0; ng < 8; ng++) {
                    const int nr = ng * 8 + gid;
                    uint32_t vh0 = *(const uint32_t*)&sVh[nr][kb];
                    uint32_t vh1 = *(const uint32_t*)&sVh[nr][kb + 8];
                    uint32_t vl0 = *(const uint32_t*)&sVl[nr][kb];
                    uint32_t vl1 = *(const uint32_t*)&sVl[nr][kb + 8];
                    MMA_BF16(O[ng], Ph, vh0, vh1);
                    MMA_BF16(O[ng], Ph, vl0, vl1);
                    MMA_BF16(O[ng], Pl, vh0, vh1);
                }
            }
        }
    }

    const int b = bh >> 4, h = bh & 15;
    #pragma unroll
    for (int hh = 0; hh < 2; hh++) {
        const float inv = 1.f / lr[hh];
        const int q = qA + hh * 8;
        const size_t base = ((size_t)(b * T_ + q)) * D_MODEL + h * DKH;
        #pragma unroll
        for (int ng = 0; ng < 8; ng++) {
            uint32_t hi, lo;
            split2(O[ng][2 * hh] * inv, O[ng][2 * hh + 1] * inv, hi, lo);
            *(uint32_t*)&g_ah[base + ng * 8 + tig * 2] = hi;
            *(uint32_t*)&g_al[base + ng * 8 + tig * 2] = lo;
        }
    }
}

// ---------------------------------------------------------------------------
extern "C" void kernel_launch(void* const* d_in, const int* in_sizes, int n_in,
                              void* d_out, int out_size)
{
    const float* x     = (const float*)d_in[0];
    const float* w_qkv = (const float*)d_in[1];
    const float* w_out = (const float*)d_in[2];
    float* out = (float*)d_out;

    static bool attr_set = false;
    if (!attr_set) {
        cudaFuncSetAttribute(gemm_mma<0>, cudaFuncAttributeMaxDynamicSharedMemorySize, GEMM_SMEM);
        cudaFuncSetAttribute(gemm_mma<1>, cudaFuncAttributeMaxDynamicSharedMemorySize, GEMM_SMEM);
        attr_set = true;
    }

    cvt_split<<<(M_TOT * GK / 4 + 255) / 256, 256>>>(x, M_TOT * GK / 4);
    cvt_split_T<0><<<dim3(N_QKV / 32, GK / 32), dim3(32, 8)>>>(w_qkv, N_QKV);
    cvt_split_T<1><<<dim3(D_MODEL / 32, GK / 32), dim3(32, 8)>>>(w_out, D_MODEL);

    gemm_mma<0><<<dim3(N_QKV / 128, M_TOT / 128), 256, GEMM_SMEM>>>(nullptr, N_QKV);
    attn_mma<<<dim3(T_ / 128, B_ * N_HEADS), 256>>>();
    gemm_mma<1><<<dim3(D_MODEL / 128, M_TOT / 128), 256, GEMM_SMEM>>>(out, D_MODEL);
}

// round 15
// speedup vs baseline: 1.1865x; 1.1865x over previous
#include <cuda_runtime.h>
#include <cuda_bf16.h>
#include <cstdint>

#define D_MODEL 1024
#define N_HEADS 16
#define DKH     64
#define B_      4
#define T_      2048
#define M_TOT   (B_ * T_)        // 8192
#define N_QKV   (3 * D_MODEL)    // 3072
#define GK      1024

// ---------------- scratch (device globals; no allocation allowed) ----------
// Q/K: bf16 hi/lo, [bh][t][dk] (Q pre-scaled by 0.125). V: [bh][dk][t].
__device__ __nv_bfloat16 g_qh[(size_t)64 * T_ * DKH];
__device__ __nv_bfloat16 g_ql[(size_t)64 * T_ * DKH];
__device__ __nv_bfloat16 g_kh[(size_t)64 * T_ * DKH];
__device__ __nv_bfloat16 g_kl[(size_t)64 * T_ * DKH];
__device__ __nv_bfloat16 g_vh[(size_t)64 * DKH * T_];
__device__ __nv_bfloat16 g_vl[(size_t)64 * DKH * T_];
__device__ float g_attn[(size_t)M_TOT * D_MODEL];

// ============================ helpers ======================================
#define MMA_BF16(D, A, b0, b1) \
    asm volatile("mma.sync.aligned.m16n8k16.row.col.f32.bf16.bf16.f32 " \
        "{%0,%1,%2,%3}, {%4,%5,%6,%7}, {%8,%9}, {%0,%1,%2,%3};" \
        : "+f"((D)[0]), "+f"((D)[1]), "+f"((D)[2]), "+f"((D)[3]) \
        : "r"((A)[0]), "r"((A)[1]), "r"((A)[2]), "r"((A)[3]), "r"(b0), "r"(b1))

__device__ __forceinline__ uint32_t smem_u32(const void* p) {
    uint32_t a;
    asm("{ .reg .u64 t; cvta.to.shared.u64 t, %1; cvt.u32.u64 %0, t; }"
        : "=r"(a) : "l"(p));
    return a;
}
#define CP16(dst, src) \
    asm volatile("cp.async.cg.shared.global [%0], [%1], 16;" \
                 :: "r"((uint32_t)(dst)), "l"(src) : "memory")
#define CP_COMMIT() asm volatile("cp.async.commit_group;" ::: "memory")
#define CP_WAIT0()  asm volatile("cp.async.wait_group 0;" ::: "memory")

__device__ __forceinline__ void bf16_split(float x, unsigned short& h, unsigned short& l)
{
    __nv_bfloat16 hb = __float2bfloat16(x);
    h = __bfloat16_as_ushort(hb);
    l = __bfloat16_as_ushort(__float2bfloat16(x - __bfloat162float(hb)));
}
__device__ __forceinline__ void split2(float a, float b, uint32_t& hi, uint32_t& lo)
{
    unsigned short ha, la, hb, lb;
    bf16_split(a, ha, la);
    bf16_split(b, hb, lb);
    hi = (uint32_t)ha | ((uint32_t)hb << 16);
    lo = (uint32_t)la | ((uint32_t)lb << 16);
}

// ===================== double-buffered bf16 HMMA GEMM (R12, proven) ========
#define BKS  16
#define NST  (GK / BKS)
#define AST  18

template<int MODE>
__global__ __launch_bounds__(256)
void gemm_mma(const float* __restrict__ Ap, const float* __restrict__ Bp,
              float* __restrict__ Cp, int N)
{
    __shared__ __nv_bfloat16 sA[2][2][128][AST];
    __shared__ __nv_bfloat16 sB[2][2][128][AST];

    const int tid  = threadIdx.x;
    const int wid  = tid >> 5;
    const int lane = tid & 31;
    const int wm   = wid & 1;
    const int wn   = wid >> 1;
    const int gid  = lane >> 2;
    const int tig  = lane & 3;
    const int row0 = blockIdx.y * 128;
    const int col0 = blockIdx.x * 128;

    const float* A = (MODE == 1) ? g_attn : Ap;

    float d[4][4][4];
    #pragma unroll
    for (int i = 0; i < 4; i++)
        #pragma unroll
        for (int j = 0; j < 4; j++)
            #pragma unroll
            for (int e = 0; e < 4; e++) d[i][j][e] = 0.f;

    const int ar0 = tid >> 2, ac0 = (tid & 3) * 4;
    float4 va[2];
    float  vb[2][4];

    #pragma unroll
    for (int i = 0; i < 2; i++)
        va[i] = *(const float4*)(A + (size_t)(row0 + ar0 + i * 64) * GK + ac0);
    #pragma unroll
    for (int jj = 0; jj < 2; jj++)
        #pragma unroll
        for (int c = 0; c < 4; c++)
            vb[jj][c] = Bp[(size_t)(wid + 8 * jj) * N + col0 + lane + 32 * c];

    #pragma unroll
    for (int i = 0; i < 2; i++) {
        const int ra = ar0 + i * 64;
        const float xs[4] = {va[i].x, va[i].y, va[i].z, va[i].w};
        #pragma unroll
        for (int j = 0; j < 2; j++) {
            uint32_t hi, lo;
            split2(xs[2 * j + 0], xs[2 * j + 1], hi, lo);
            *(uint32_t*)&sA[0][0][ra][ac0 + 2 * j] = hi;
            *(uint32_t*)&sA[0][1][ra][ac0 + 2 * j] = lo;
        }
    }
    #pragma unroll
    for (int jj = 0; jj < 2; jj++)
        #pragma unroll
        for (int c = 0; c < 4; c++) {
            unsigned short hh, ll;
            bf16_split(vb[jj][c], hh, ll);
            sB[0][0][lane + 32 * c][wid + 8 * jj] = __ushort_as_bfloat16(hh);
            sB[0][1][lane + 32 * c][wid + 8 * jj] = __ushort_as_bfloat16(ll);
        }
    __syncthreads();

    const int kb = tig * 2;
    for (int kt = 0; kt < NST; kt++) {
        const int buf = kt & 1;
        if (kt + 1 < NST) {
            const int k0 = (kt + 1) * BKS;
            #pragma unroll
            for (int i = 0; i < 2; i++)
                va[i] = *(const float4*)(A + (size_t)(row0 + ar0 + i * 64) * GK + k0 + ac0);
            #pragma unroll
            for (int jj = 0; jj < 2; jj++)
                #pragma unroll
                for (int c = 0; c < 4; c++)
                    vb[jj][c] = Bp[(size_t)(k0 + wid + 8 * jj) * N + col0 + lane + 32 * c];
        }

        uint32_t Ah[4][4], Al[4][4];
        #pragma unroll
        for (int mi = 0; mi < 4; mi++) {
            const int r0 = wm * 64 + mi * 16 + gid;
            Ah[mi][0] = *(const uint32_t*)&sA[buf][0][r0][kb];
            Ah[mi][1] = *(const uint32_t*)&sA[buf][0][r0 + 8][kb];
            Ah[mi][2] = *(const uint32_t*)&sA[buf][0][r0][kb + 8];
            Ah[mi][3] = *(const uint32_t*)&sA[buf][0][r0 + 8][kb + 8];
            Al[mi][0] = *(const uint32_t*)&sA[buf][1][r0][kb];
            Al[mi][1] = *(const uint32_t*)&sA[buf][1][r0 + 8][kb];
            Al[mi][2] = *(const uint32_t*)&sA[buf][1][r0][kb + 8];
            Al[mi][3] = *(const uint32_t*)&sA[buf][1][r0 + 8][kb + 8];
        }
        uint32_t Bh[4][2], Bl[4][2];
        #pragma unroll
        for (int ng = 0; ng < 4; ng++) {
            const int nr = wn * 32 + ng * 8 + gid;
            Bh[ng][0] = *(const uint32_t*)&sB[buf][0][nr][kb];
            Bh[ng][1] = *(const uint32_t*)&sB[buf][0][nr][kb + 8];
            Bl[ng][0] = *(const uint32_t*)&sB[buf][1][nr][kb];
            Bl[ng][1] = *(const uint32_t*)&sB[buf][1][nr][kb + 8];
        }
        #pragma unroll
        for (int mi = 0; mi < 4; mi++)
            #pragma unroll
            for (int ng = 0; ng < 4; ng++) {
                MMA_BF16(d[mi][ng], Ah[mi], Bh[ng][0], Bh[ng][1]);
                MMA_BF16(d[mi][ng], Ah[mi], Bl[ng][0], Bl[ng][1]);
                MMA_BF16(d[mi][ng], Al[mi], Bh[ng][0], Bh[ng][1]);
            }

        if (kt + 1 < NST) {
            const int nb = buf ^ 1;
            #pragma unroll
            for (int i = 0; i < 2; i++) {
                const int ra = ar0 + i * 64;
                const float xs[4] = {va[i].x, va[i].y, va[i].z, va[i].w};
                #pragma unroll
                for (int j = 0; j < 2; j++) {
                    uint32_t hi, lo;
                    split2(xs[2 * j + 0], xs[2 * j + 1], hi, lo);
                    *(uint32_t*)&sA[nb][0][ra][ac0 + 2 * j] = hi;
                    *(uint32_t*)&sA[nb][1][ra][ac0 + 2 * j] = lo;
                }
            }
            #pragma unroll
            for (int jj = 0; jj < 2; jj++)
                #pragma unroll
                for (int c = 0; c < 4; c++) {
                    unsigned short hh, ll;
                    bf16_split(vb[jj][c], hh, ll);
                    sB[nb][0][lane + 32 * c][wid + 8 * jj] = __ushort_as_bfloat16(hh);
                    sB[nb][1][lane + 32 * c][wid + 8 * jj] = __ushort_as_bfloat16(ll);
                }
        }
        __syncthreads();
    }

    // ---------------- epilogue ----------------
    #pragma unroll
    for (int mi = 0; mi < 4; mi++)
        #pragma unroll
        for (int ng = 0; ng < 4; ng++) {
            const int n = col0 + wn * 32 + ng * 8 + tig * 2;
            #pragma unroll
            for (int h = 0; h < 2; h++) {
                const int m = row0 + wm * 64 + mi * 16 + gid + h * 8;
                float2 v;
                v.x = d[mi][ng][h * 2 + 0];
                v.y = d[mi][ng][h * 2 + 1];
                if (MODE == 0) {
                    const int b = m >> 11, t = m & (T_ - 1);
                    const int sidx = n >> 10;
                    const int dmi  = n & (D_MODEL - 1);
                    const int hh = dmi >> 6, dk = dmi & (DKH - 1);
                    const int bh = (b << 4) + hh;
                    if (sidx == 0) {
                        uint32_t hi, lo;
                        split2(0.125f * v.x, 0.125f * v.y, hi, lo);
                        const size_t idx = ((size_t)bh * T_ + t) * DKH + dk;
                        *(uint32_t*)&g_qh[idx] = hi;
                        *(uint32_t*)&g_ql[idx] = lo;
                    } else if (sidx == 1) {
                        uint32_t hi, lo;
                        split2(v.x, v.y, hi, lo);
                        const size_t idx = ((size_t)bh * T_ + t) * DKH + dk;
                        *(uint32_t*)&g_kh[idx] = hi;
                        *(uint32_t*)&g_kl[idx] = lo;
                    } else {
                        unsigned short h0, l0, h1, l1;
                        bf16_split(v.x, h0, l0);
                        bf16_split(v.y, h1, l1);
                        const size_t i0 = ((size_t)bh * DKH + dk) * T_ + t;
                        g_vh[i0] = __ushort_as_bfloat16(h0);
                        g_vl[i0] = __ushort_as_bfloat16(l0);
                        g_vh[i0 + T_] = __ushort_as_bfloat16(h1);
                        g_vl[i0 + T_] = __ushort_as_bfloat16(l1);
                    }
                } else {
                    *(float2*)(Cp + (size_t)m * N + n) = v;
                }
            }
        }
}

// ===================== bf16 HMMA causal flash attention ====================
// 128 q-rows/CTA, 8 warps x 16 rows, 64-key tiles. Pre-split inputs.
// 2-stage cp.async K/V pipeline: 1 barrier/tile, loads overlap MMA.
#define VST 72
#define ATILE  (64 * VST * 2)     // 9216 B per array
#define ASTAGE (4 * ATILE)        // 36864 B per stage (Kh,Kl,Vh,Vl)
#define ATTN_SMEM (2 * ASTAGE)    // 73728 B

__global__ __launch_bounds__(256, 2)
void attn_mma()
{
    extern __shared__ __align__(16) char smem[];

    const int bh  = blockIdx.y;
    const int q0  = blockIdx.x * 128;
    const int tid = threadIdx.x;
    const int wid = tid >> 5;
    const int lane = tid & 31;
    const int gid = lane >> 2;
    const int tig = lane & 3;

    const __nv_bfloat16* Qh_g = g_qh + ((size_t)bh * T_ + q0) * DKH;
    const __nv_bfloat16* Ql_g = g_ql + ((size_t)bh * T_ + q0) * DKH;
    const __nv_bfloat16* Kh_g = g_kh + (size_t)bh * T_ * DKH;
    const __nv_bfloat16* Kl_g = g_kl + (size_t)bh * T_ * DKH;
    const __nv_bfloat16* Vh_g = g_vh + (size_t)bh * DKH * T_;
    const __nv_bfloat16* Vl_g = g_vl + (size_t)bh * DKH * T_;
    const float LOG2E = 1.4426950408889634f;
    const uint32_t sb = smem_u32(smem);

    // ---- Q fragments (staged through stage-0 K arrays, two 64-row passes) --
    uint32_t Qh[4][4], Ql[4][4];
    {
        __nv_bfloat16* tKh = (__nv_bfloat16*)(smem);
        __nv_bfloat16* tKl = (__nv_bfloat16*)(smem + ATILE);
        #pragma unroll
        for (int pass = 0; pass < 2; pass++) {
            #pragma unroll
            for (int i = 0; i < 2; i++) {
                const int c = tid + i * 256;
                const int rr = c >> 3, cc = (c & 7) * 8;
                *(uint4*)&tKh[rr * VST + cc] =
                    *(const uint4*)(Qh_g + (size_t)(pass * 64 + rr) * DKH + cc);
                *(uint4*)&tKl[rr * VST + cc] =
                    *(const uint4*)(Ql_g + (size_t)(pass * 64 + rr) * DKH + cc);
            }
            __syncthreads();
            if ((wid >> 2) == pass) {
                const int rb = (wid & 3) * 16 + gid;
                #pragma unroll
                for (int ks = 0; ks < 4; ks++) {
                    const int kb = ks * 16 + tig * 2;
                    Qh[ks][0] = *(const uint32_t*)&tKh[rb * VST + kb];
                    Qh[ks][1] = *(const uint32_t*)&tKh[(rb + 8) * VST + kb];
                    Qh[ks][2] = *(const uint32_t*)&tKh[rb * VST + kb + 8];
                    Qh[ks][3] = *(const uint32_t*)&tKh[(rb + 8) * VST + kb + 8];
                    Ql[ks][0] = *(const uint32_t*)&tKl[rb * VST + kb];
                    Ql[ks][1] = *(const uint32_t*)&tKl[(rb + 8) * VST + kb];
                    Ql[ks][2] = *(const uint32_t*)&tKl[rb * VST + kb + 8];
                    Ql[ks][3] = *(const uint32_t*)&tKl[(rb + 8) * VST + kb + 8];
                }
            }
            __syncthreads();
        }
    }

    float O[8][4];
    #pragma unroll
    for (int i = 0; i < 8; i++)
        #pragma unroll
        for (int e = 0; e < 4; e++) O[i][e] = 0.f;
    float mr[2] = {-1e30f, -1e30f}, lr[2] = {0.f, 0.f};

    const int qA = q0 + wid * 16 + gid;
    const int ntiles = (q0 >> 6) + 2;

    // cp.async issue of tile t into stage s
    auto issue = [&](int t, int s) {
        const int k0 = t * 64;
        const uint32_t base = sb + (uint32_t)s * ASTAGE;
        #pragma unroll
        for (int i = 0; i < 2; i++) {
            const int c = tid + i * 256;
            const int rr = c >> 3, cc = (c & 7) * 8;
            const uint32_t ro = (uint32_t)(rr * VST + cc) * 2;
            CP16(base + 0 * ATILE + ro, Kh_g + (size_t)(k0 + rr) * DKH + cc);
            CP16(base + 1 * ATILE + ro, Kl_g + (size_t)(k0 + rr) * DKH + cc);
            CP16(base + 2 * ATILE + ro, Vh_g + (size_t)rr * T_ + k0 + cc);
            CP16(base + 3 * ATILE + ro, Vl_g + (size_t)rr * T_ + k0 + cc);
        }
        CP_COMMIT();
    };

    issue(0, 0);

    for (int t = 0; t < ntiles; t++) {
        const int k0 = t * 64;
        CP_WAIT0();          // tile t resident
        __syncthreads();     // everyone past compute(t-1), tile t visible
        if (t + 1 < ntiles) issue(t + 1, (t + 1) & 1);

        if (k0 <= q0 + wid * 16 + 15) {
            const char* stg = smem + (t & 1) * ASTAGE;
            const __nv_bfloat16* sKh = (const __nv_bfloat16*)(stg);
            const __nv_bfloat16* sKl = (const __nv_bfloat16*)(stg + ATILE);
            const __nv_bfloat16* sVh = (const __nv_bfloat16*)(stg + 2 * ATILE);
            const __nv_bfloat16* sVl = (const __nv_bfloat16*)(stg + 3 * ATILE);

            float S[8][4];
            #pragma unroll
            for (int i = 0; i < 8; i++)
                #pragma unroll
                for (int e = 0; e < 4; e++) S[i][e] = 0.f;
            #pragma unroll
            for (int ks = 0; ks < 4; ks++) {
                const int kb = ks * 16 + tig * 2;
                #pragma unroll
                for (int ng = 0; ng < 8; ng++) {
                    const int nr = ng * 8 + gid;
                    uint32_t bh0 = *(const uint32_t*)&sKh[nr * VST + kb];
                    uint32_t bh1 = *(const uint32_t*)&sKh[nr * VST + kb + 8];
                    uint32_t bl0 = *(const uint32_t*)&sKl[nr * VST + kb];
                    uint32_t bl1 = *(const uint32_t*)&sKl[nr * VST + kb + 8];
                    MMA_BF16(S[ng], Qh[ks], bh0, bh1);
                    MMA_BF16(S[ng], Qh[ks], bl0, bl1);
                    MMA_BF16(S[ng], Ql[ks], bh0, bh1);
                }
            }
            if (k0 + 63 > q0 + wid * 16) {
                #pragma unroll
                for (int ng = 0; ng < 8; ng++)
                    #pragma unroll
                    for (int e = 0; e < 4; e++) {
                        const int key = k0 + ng * 8 + tig * 2 + (e & 1);
                        const int q   = qA + (e >> 1) * 8;
                        if (key > q) S[ng][e] = -1e30f;
                    }
            }
            #pragma unroll
            for (int h = 0; h < 2; h++) {
                float mt = -1e30f;
                #pragma unroll
                for (int ng = 0; ng < 8; ng++)
                    mt = fmaxf(mt, fmaxf(S[ng][2 * h], S[ng][2 * h + 1]));
                mt = fmaxf(mt, __shfl_xor_sync(0xffffffff, mt, 1));
                mt = fmaxf(mt, __shfl_xor_sync(0xffffffff, mt, 2));
                const float mn = fmaxf(mr[h], mt);
                const float alpha = exp2f((mr[h] - mn) * LOG2E);
                float rs = 0.f;
                #pragma unroll
                for (int ng = 0; ng < 8; ng++) {
                    float p0 = exp2f((S[ng][2 * h] - mn) * LOG2E);
                    float p1 = exp2f((S[ng][2 * h + 1] - mn) * LOG2E);
                    S[ng][2 * h] = p0;
                    S[ng][2 * h + 1] = p1;
                    rs += p0 + p1;
                }
                rs += __shfl_xor_sync(0xffffffff, rs, 1);
                rs += __shfl_xor_sync(0xffffffff, rs, 2);
                lr[h] = lr[h] * alpha + rs;
                mr[h] = mn;
                #pragma unroll
                for (int ng = 0; ng < 8; ng++) {
                    O[ng][2 * h] *= alpha;
                    O[ng][2 * h + 1] *= alpha;
                }
            }
            #pragma unroll
            for (int ks = 0; ks < 4; ks++) {
                uint32_t Ph[4], Pl[4];
                split2(S[2 * ks][0],     S[2 * ks][1],     Ph[0], Pl[0]);
                split2(S[2 * ks][2],     S[2 * ks][3],     Ph[1], Pl[1]);
                split2(S[2 * ks + 1][0], S[2 * ks + 1][1], Ph[2], Pl[2]);
                split2(S[2 * ks + 1][2], S[2 * ks + 1][3], Ph[3], Pl[3]);
                const int kb = ks * 16 + tig * 2;
                #pragma unroll
                for (int ng = 0; ng < 8; ng++) {
                    const int nr = ng * 8 + gid;
                    uint32_t vh0 = *(const uint32_t*)&sVh[nr * VST + kb];
                    uint32_t vh1 = *(const uint32_t*)&sVh[nr * VST + kb + 8];
                    uint32_t vl0 = *(const uint32_t*)&sVl[nr * VST + kb];
                    uint32_t vl1 = *(const uint32_t*)&sVl[nr * VST + kb + 8];
                    MMA_BF16(O[ng], Ph, vh0, vh1);
                    MMA_BF16(O[ng], Ph, vl0, vl1);
                    MMA_BF16(O[ng], Pl, vh0, vh1);
                }
            }
        }
    }

    // ---- epilogue: normalize + write (B,T,D) fp32 ----
    const int b = bh >> 4, h = bh & 15;
    #pragma unroll
    for (int hh = 0; hh < 2; hh++) {
        const float inv = 1.f / lr[hh];
        const int q = qA + hh * 8;
        float* og = g_attn + ((size_t)(b * T_ + q)) * D_MODEL + h * DKH;
        #pragma unroll
        for (int ng = 0; ng < 8; ng++) {
            float2 v;
            v.x = O[ng][2 * hh] * inv;
            v.y = O[ng][2 * hh + 1] * inv;
            *(float2*)(og + ng * 8 + tig * 2) = v;
        }
    }
}

// ---------------------------------------------------------------------------
extern "C" void kernel_launch(void* const* d_in, const int* in_sizes, int n_in,
                              void* d_out, int out_size)
{
    const float* x     = (const float*)d_in[0];
    const float* w_qkv = (const float*)d_in[1];
    const float* w_out = (const float*)d_in[2];
    float* out = (float*)d_out;

    static bool attr_set = false;
    if (!attr_set) {
        cudaFuncSetAttribute(attn_mma, cudaFuncAttributeMaxDynamicSharedMemorySize,
                             ATTN_SMEM);
        attr_set = true;
    }

    gemm_mma<0><<<dim3(N_QKV / 128, M_TOT / 128), 256>>>(x, w_qkv, nullptr, N_QKV);
    attn_mma<<<dim3(T_ / 128, B_ * N_HEADS), 256, ATTN_SMEM>>>();
    gemm_mma<1><<<dim3(D_MODEL / 128, M_TOT / 128), 256>>>(nullptr, w_out, out, D_MODEL);
}

// round 16
// speedup vs baseline: 1.2130x; 1.0223x over previous
#include <cuda_runtime.h>
#include <cuda_bf16.h>
#include <cstdint>

#define D_MODEL 1024
#define N_HEADS 16
#define DKH     64
#define B_      4
#define T_      2048
#define M_TOT   (B_ * T_)        // 8192
#define N_QKV   (3 * D_MODEL)    // 3072
#define GK      1024

// ---------------- scratch (device globals; no allocation allowed) ----------
__device__ __nv_bfloat16 g_qh[(size_t)64 * T_ * DKH];
__device__ __nv_bfloat16 g_ql[(size_t)64 * T_ * DKH];
__device__ __nv_bfloat16 g_kh[(size_t)64 * T_ * DKH];
__device__ __nv_bfloat16 g_kl[(size_t)64 * T_ * DKH];
__device__ __nv_bfloat16 g_vh[(size_t)64 * DKH * T_];
__device__ __nv_bfloat16 g_vl[(size_t)64 * DKH * T_];
__device__ float g_attn[(size_t)M_TOT * D_MODEL];

// ============================ helpers ======================================
#define MMA_BF16(D, A, b0, b1) \
    asm volatile("mma.sync.aligned.m16n8k16.row.col.f32.bf16.bf16.f32 " \
        "{%0,%1,%2,%3}, {%4,%5,%6,%7}, {%8,%9}, {%0,%1,%2,%3};" \
        : "+f"((D)[0]), "+f"((D)[1]), "+f"((D)[2]), "+f"((D)[3]) \
        : "r"((A)[0]), "r"((A)[1]), "r"((A)[2]), "r"((A)[3]), "r"(b0), "r"(b1))

#define LDSM_X4(R, a) \
    asm volatile("ldmatrix.sync.aligned.m8n8.x4.shared.b16 {%0,%1,%2,%3}, [%4];" \
        : "=r"((R)[0]), "=r"((R)[1]), "=r"((R)[2]), "=r"((R)[3]) : "r"(a))

__device__ __forceinline__ uint32_t smem_u32(const void* p) {
    uint32_t a;
    asm("{ .reg .u64 t; cvta.to.shared.u64 t, %1; cvt.u32.u64 %0, t; }"
        : "=r"(a) : "l"(p));
    return a;
}
#define CP16(dst, src) \
    asm volatile("cp.async.cg.shared.global [%0], [%1], 16;" \
                 :: "r"((uint32_t)(dst)), "l"(src) : "memory")
#define CP_COMMIT() asm volatile("cp.async.commit_group;" ::: "memory")
#define CP_WAIT0()  asm volatile("cp.async.wait_group 0;" ::: "memory")

__device__ __forceinline__ void bf16_split(float x, unsigned short& h, unsigned short& l)
{
    __nv_bfloat16 hb = __float2bfloat16(x);
    h = __bfloat16_as_ushort(hb);
    l = __bfloat16_as_ushort(__float2bfloat16(x - __bfloat162float(hb)));
}
__device__ __forceinline__ void split2(float a, float b, uint32_t& hi, uint32_t& lo)
{
    unsigned short ha, la, hb, lb;
    bf16_split(a, ha, la);
    bf16_split(b, hb, lb);
    hi = (uint32_t)ha | ((uint32_t)hb << 16);
    lo = (uint32_t)la | ((uint32_t)lb << 16);
}

// ===================== double-buffered bf16 HMMA GEMM ======================
// C = AhBh + AhBl + AlBh. CTA 128x128, 8 warps 2x4, warp 64x32, BK=16.
// Fragments via ldmatrix.x4 (12 LDSM/warp/stage vs 48 LDS.32).
// Smem stride 24 bf16 = 48 B rows (16B-aligned, ldmatrix conflict-free).
#define BKS  16
#define NST  (GK / BKS)
#define AST  24
#define ROWB (AST * 2)            // 48 bytes per row
#define HOFF (128 * ROWB)         // hi->lo array offset 6144 B
#define BUFO (2 * HOFF)           // buffer offset 12288 B

template<int MODE>
__global__ __launch_bounds__(256)
void gemm_mma(const float* __restrict__ Ap, const float* __restrict__ Bp,
              float* __restrict__ Cp, int N)
{
    __shared__ __nv_bfloat16 sA[2][2][128][AST];   // 24 KB
    __shared__ __nv_bfloat16 sB[2][2][128][AST];   // 24 KB

    const int tid  = threadIdx.x;
    const int wid  = tid >> 5;
    const int lane = tid & 31;
    const int wm   = wid & 1;
    const int wn   = wid >> 1;
    const int gid  = lane >> 2;
    const int tig  = lane & 3;
    const int row0 = blockIdx.y * 128;
    const int col0 = blockIdx.x * 128;

    const float* A = (MODE == 1) ? g_attn : Ap;

    float d[4][4][4];
    #pragma unroll
    for (int i = 0; i < 4; i++)
        #pragma unroll
        for (int j = 0; j < 4; j++)
            #pragma unroll
            for (int e = 0; e < 4; e++) d[i][j][e] = 0.f;

    const int ar0 = tid >> 2, ac0 = (tid & 3) * 4;
    float4 va[2];
    float  vb[2][4];

    // ldmatrix lane addressing (byte offsets within an array)
    const uint32_t uA0 = smem_u32(&sA[0][0][0][0]);
    const uint32_t uB0 = smem_u32(&sB[0][0][0][0]);
    // A: lanes 0-15 -> rows m0-15, lanes 16-31 -> same rows at k+8
    const uint32_t a_lo = (uint32_t)((lane & 15) * ROWB + ((lane >> 4) << 4))
                        + (uint32_t)(wm * 64 * ROWB);
    // B: matrices (ng, k0), (ng, k8), (ng+1, k0), (ng+1, k8)
    const uint32_t b_lo = (uint32_t)(((lane >> 4) * 8 + (lane & 7)) * ROWB
                        + (((lane >> 3) & 1) << 4))
                        + (uint32_t)(wn * 32 * ROWB);

    // ---- prologue: load + store stage 0 ----
    #pragma unroll
    for (int i = 0; i < 2; i++)
        va[i] = *(const float4*)(A + (size_t)(row0 + ar0 + i * 64) * GK + ac0);
    #pragma unroll
    for (int jj = 0; jj < 2; jj++)
        #pragma unroll
        for (int c = 0; c < 4; c++)
            vb[jj][c] = Bp[(size_t)(wid + 8 * jj) * N + col0 + lane + 32 * c];

    #pragma unroll
    for (int i = 0; i < 2; i++) {
        const int ra = ar0 + i * 64;
        const float xs[4] = {va[i].x, va[i].y, va[i].z, va[i].w};
        #pragma unroll
        for (int j = 0; j < 2; j++) {
            uint32_t hi, lo;
            split2(xs[2 * j + 0], xs[2 * j + 1], hi, lo);
            *(uint32_t*)&sA[0][0][ra][ac0 + 2 * j] = hi;
            *(uint32_t*)&sA[0][1][ra][ac0 + 2 * j] = lo;
        }
    }
    #pragma unroll
    for (int jj = 0; jj < 2; jj++)
        #pragma unroll
        for (int c = 0; c < 4; c++) {
            unsigned short hh, ll;
            bf16_split(vb[jj][c], hh, ll);
            sB[0][0][lane + 32 * c][wid + 8 * jj] = __ushort_as_bfloat16(hh);
            sB[0][1][lane + 32 * c][wid + 8 * jj] = __ushort_as_bfloat16(ll);
        }
    __syncthreads();

    for (int kt = 0; kt < NST; kt++) {
        const int buf = kt & 1;
        // ---- prefetch stage kt+1 ----
        if (kt + 1 < NST) {
            const int k0 = (kt + 1) * BKS;
            #pragma unroll
            for (int i = 0; i < 2; i++)
                va[i] = *(const float4*)(A + (size_t)(row0 + ar0 + i * 64) * GK + k0 + ac0);
            #pragma unroll
            for (int jj = 0; jj < 2; jj++)
                #pragma unroll
                for (int c = 0; c < 4; c++)
                    vb[jj][c] = Bp[(size_t)(k0 + wid + 8 * jj) * N + col0 + lane + 32 * c];
        }

        // ---- fragment loads via ldmatrix ----
        const uint32_t aBase = uA0 + buf * BUFO + a_lo;
        const uint32_t bBase = uB0 + buf * BUFO + b_lo;
        uint32_t Ah[4][4], Al[4][4];
        #pragma unroll
        for (int mi = 0; mi < 4; mi++) {
            LDSM_X4(Ah[mi], aBase + mi * (16 * ROWB));
            LDSM_X4(Al[mi], aBase + mi * (16 * ROWB) + HOFF);
        }
        uint32_t Bh[4][2], Bl[4][2];
        #pragma unroll
        for (int p = 0; p < 2; p++) {
            uint32_t rh[4], rl[4];
            LDSM_X4(rh, bBase + p * (16 * ROWB));
            LDSM_X4(rl, bBase + p * (16 * ROWB) + HOFF);
            Bh[2 * p][0] = rh[0]; Bh[2 * p][1] = rh[1];
            Bh[2 * p + 1][0] = rh[2]; Bh[2 * p + 1][1] = rh[3];
            Bl[2 * p][0] = rl[0]; Bl[2 * p][1] = rl[1];
            Bl[2 * p + 1][0] = rl[2]; Bl[2 * p + 1][1] = rl[3];
        }
        #pragma unroll
        for (int mi = 0; mi < 4; mi++)
            #pragma unroll
            for (int ng = 0; ng < 4; ng++) {
                MMA_BF16(d[mi][ng], Ah[mi], Bh[ng][0], Bh[ng][1]);
                MMA_BF16(d[mi][ng], Ah[mi], Bl[ng][0], Bl[ng][1]);
                MMA_BF16(d[mi][ng], Al[mi], Bh[ng][0], Bh[ng][1]);
            }

        // ---- store stage kt+1 ----
        if (kt + 1 < NST) {
            const int nb = buf ^ 1;
            #pragma unroll
            for (int i = 0; i < 2; i++) {
                const int ra = ar0 + i * 64;
                const float xs[4] = {va[i].x, va[i].y, va[i].z, va[i].w};
                #pragma unroll
                for (int j = 0; j < 2; j++) {
                    uint32_t hi, lo;
                    split2(xs[2 * j + 0], xs[2 * j + 1], hi, lo);
                    *(uint32_t*)&sA[nb][0][ra][ac0 + 2 * j] = hi;
                    *(uint32_t*)&sA[nb][1][ra][ac0 + 2 * j] = lo;
                }
            }
            #pragma unroll
            for (int jj = 0; jj < 2; jj++)
                #pragma unroll
                for (int c = 0; c < 4; c++) {
                    unsigned short hh, ll;
                    bf16_split(vb[jj][c], hh, ll);
                    sB[nb][0][lane + 32 * c][wid + 8 * jj] = __ushort_as_bfloat16(hh);
                    sB[nb][1][lane + 32 * c][wid + 8 * jj] = __ushort_as_bfloat16(ll);
                }
        }
        __syncthreads();
    }

    // ---------------- epilogue ----------------
    #pragma unroll
    for (int mi = 0; mi < 4; mi++)
        #pragma unroll
        for (int ng = 0; ng < 4; ng++) {
            const int n = col0 + wn * 32 + ng * 8 + tig * 2;
            #pragma unroll
            for (int h = 0; h < 2; h++) {
                const int m = row0 + wm * 64 + mi * 16 + gid + h * 8;
                float2 v;
                v.x = d[mi][ng][h * 2 + 0];
                v.y = d[mi][ng][h * 2 + 1];
                if (MODE == 0) {
                    const int b = m >> 11, t = m & (T_ - 1);
                    const int sidx = n >> 10;
                    const int dmi  = n & (D_MODEL - 1);
                    const int hh = dmi >> 6, dk = dmi & (DKH - 1);
                    const int bh = (b << 4) + hh;
                    if (sidx == 0) {
                        uint32_t hi, lo;
                        split2(0.125f * v.x, 0.125f * v.y, hi, lo);
                        const size_t idx = ((size_t)bh * T_ + t) * DKH + dk;
                        *(uint32_t*)&g_qh[idx] = hi;
                        *(uint32_t*)&g_ql[idx] = lo;
                    } else if (sidx == 1) {
                        uint32_t hi, lo;
                        split2(v.x, v.y, hi, lo);
                        const size_t idx = ((size_t)bh * T_ + t) * DKH + dk;
                        *(uint32_t*)&g_kh[idx] = hi;
                        *(uint32_t*)&g_kl[idx] = lo;
                    } else {
                        unsigned short h0, l0, h1, l1;
                        bf16_split(v.x, h0, l0);
                        bf16_split(v.y, h1, l1);
                        const size_t i0 = ((size_t)bh * DKH + dk) * T_ + t;
                        g_vh[i0] = __ushort_as_bfloat16(h0);
                        g_vl[i0] = __ushort_as_bfloat16(l0);
                        g_vh[i0 + T_] = __ushort_as_bfloat16(h1);
                        g_vl[i0 + T_] = __ushort_as_bfloat16(l1);
                    }
                } else {
                    *(float2*)(Cp + (size_t)m * N + n) = v;
                }
            }
        }
}

// ===================== bf16 HMMA causal flash attention (R15, proven) ======
#define VST 72
#define ATILE  (64 * VST * 2)     // 9216 B per array
#define ASTAGE (4 * ATILE)        // 36864 B per stage
#define ATTN_SMEM (2 * ASTAGE)    // 73728 B

__global__ __launch_bounds__(256, 2)
void attn_mma()
{
    extern __shared__ __align__(16) char smem[];

    const int bh  = blockIdx.y;
    const int q0  = blockIdx.x * 128;
    const int tid = threadIdx.x;
    const int wid = tid >> 5;
    const int lane = tid & 31;
    const int gid = lane >> 2;
    const int tig = lane & 3;

    const __nv_bfloat16* Qh_g = g_qh + ((size_t)bh * T_ + q0) * DKH;
    const __nv_bfloat16* Ql_g = g_ql + ((size_t)bh * T_ + q0) * DKH;
    const __nv_bfloat16* Kh_g = g_kh + (size_t)bh * T_ * DKH;
    const __nv_bfloat16* Kl_g = g_kl + (size_t)bh * T_ * DKH;
    const __nv_bfloat16* Vh_g = g_vh + (size_t)bh * DKH * T_;
    const __nv_bfloat16* Vl_g = g_vl + (size_t)bh * DKH * T_;
    const float LOG2E = 1.4426950408889634f;
    const uint32_t sb = smem_u32(smem);

    // ---- Q fragments (staged through stage-0 K arrays, two 64-row passes) --
    uint32_t Qh[4][4], Ql[4][4];
    {
        __nv_bfloat16* tKh = (__nv_bfloat16*)(smem);
        __nv_bfloat16* tKl = (__nv_bfloat16*)(smem + ATILE);
        #pragma unroll
        for (int pass = 0; pass < 2; pass++) {
            #pragma unroll
            for (int i = 0; i < 2; i++) {
                const int c = tid + i * 256;
                const int rr = c >> 3, cc = (c & 7) * 8;
                *(uint4*)&tKh[rr * VST + cc] =
                    *(const uint4*)(Qh_g + (size_t)(pass * 64 + rr) * DKH + cc);
                *(uint4*)&tKl[rr * VST + cc] =
                    *(const uint4*)(Ql_g + (size_t)(pass * 64 + rr) * DKH + cc);
            }
            __syncthreads();
            if ((wid >> 2) == pass) {
                const int rb = (wid & 3) * 16 + gid;
                #pragma unroll
                for (int ks = 0; ks < 4; ks++) {
                    const int kb = ks * 16 + tig * 2;
                    Qh[ks][0] = *(const uint32_t*)&tKh[rb * VST + kb];
                    Qh[ks][1] = *(const uint32_t*)&tKh[(rb + 8) * VST + kb];
                    Qh[ks][2] = *(const uint32_t*)&tKh[rb * VST + kb + 8];
                    Qh[ks][3] = *(const uint32_t*)&tKh[(rb + 8) * VST + kb + 8];
                    Ql[ks][0] = *(const uint32_t*)&tKl[rb * VST + kb];
                    Ql[ks][1] = *(const uint32_t*)&tKl[(rb + 8) * VST + kb];
                    Ql[ks][2] = *(const uint32_t*)&tKl[rb * VST + kb + 8];
                    Ql[ks][3] = *(const uint32_t*)&tKl[(rb + 8) * VST + kb + 8];
                }
            }
            __syncthreads();
        }
    }

    float O[8][4];
    #pragma unroll
    for (int i = 0; i < 8; i++)
        #pragma unroll
        for (int e = 0; e < 4; e++) O[i][e] = 0.f;
    float mr[2] = {-1e30f, -1e30f}, lr[2] = {0.f, 0.f};

    const int qA = q0 + wid * 16 + gid;
    const int ntiles = (q0 >> 6) + 2;

    auto issue = [&](int t, int s) {
        const int k0 = t * 64;
        const uint32_t base = sb + (uint32_t)s * ASTAGE;
        #pragma unroll
        for (int i = 0; i < 2; i++) {
            const int c = tid + i * 256;
            const int rr = c >> 3, cc = (c & 7) * 8;
            const uint32_t ro = (uint32_t)(rr * VST + cc) * 2;
            CP16(base + 0 * ATILE + ro, Kh_g + (size_t)(k0 + rr) * DKH + cc);
            CP16(base + 1 * ATILE + ro, Kl_g + (size_t)(k0 + rr) * DKH + cc);
            CP16(base + 2 * ATILE + ro, Vh_g + (size_t)rr * T_ + k0 + cc);
            CP16(base + 3 * ATILE + ro, Vl_g + (size_t)rr * T_ + k0 + cc);
        }
        CP_COMMIT();
    };

    issue(0, 0);

    for (int t = 0; t < ntiles; t++) {
        const int k0 = t * 64;
        CP_WAIT0();
        __syncthreads();
        if (t + 1 < ntiles) issue(t + 1, (t + 1) & 1);

        if (k0 <= q0 + wid * 16 + 15) {
            const char* stg = smem + (t & 1) * ASTAGE;
            const __nv_bfloat16* sKh = (const __nv_bfloat16*)(stg);
            const __nv_bfloat16* sKl = (const __nv_bfloat16*)(stg + ATILE);
            const __nv_bfloat16* sVh = (const __nv_bfloat16*)(stg + 2 * ATILE);
            const __nv_bfloat16* sVl = (const __nv_bfloat16*)(stg + 3 * ATILE);

            float S[8][4];
            #pragma unroll
            for (int i = 0; i < 8; i++)
                #pragma unroll
                for (int e = 0; e < 4; e++) S[i][e] = 0.f;
            #pragma unroll
            for (int ks = 0; ks < 4; ks++) {
                const int kb = ks * 16 + tig * 2;
                #pragma unroll
                for (int ng = 0; ng < 8; ng++) {
                    const int nr = ng * 8 + gid;
                    uint32_t bh0 = *(const uint32_t*)&sKh[nr * VST + kb];
                    uint32_t bh1 = *(const uint32_t*)&sKh[nr * VST + kb + 8];
                    uint32_t bl0 = *(const uint32_t*)&sKl[nr * VST + kb];
                    uint32_t bl1 = *(const uint32_t*)&sKl[nr * VST + kb + 8];
                    MMA_BF16(S[ng], Qh[ks], bh0, bh1);
                    MMA_BF16(S[ng], Qh[ks], bl0, bl1);
                    MMA_BF16(S[ng], Ql[ks], bh0, bh1);
                }
            }
            if (k0 + 63 > q0 + wid * 16) {
                #pragma unroll
                for (int ng = 0; ng < 8; ng++)
                    #pragma unroll
                    for (int e = 0; e < 4; e++) {
                        const int key = k0 + ng * 8 + tig * 2 + (e & 1);
                        const int q   = qA + (e >> 1) * 8;
                        if (key > q) S[ng][e] = -1e30f;
                    }
            }
            #pragma unroll
            for (int h = 0; h < 2; h++) {
                float mt = -1e30f;
                #pragma unroll
                for (int ng = 0; ng < 8; ng++)
                    mt = fmaxf(mt, fmaxf(S[ng][2 * h], S[ng][2 * h + 1]));
                mt = fmaxf(mt, __shfl_xor_sync(0xffffffff, mt, 1));
                mt = fmaxf(mt, __shfl_xor_sync(0xffffffff, mt, 2));
                const float mn = fmaxf(mr[h], mt);
                const float alpha = exp2f((mr[h] - mn) * LOG2E);
                float rs = 0.f;
                #pragma unroll
                for (int ng = 0; ng < 8; ng++) {
                    float p0 = exp2f((S[ng][2 * h] - mn) * LOG2E);
                    float p1 = exp2f((S[ng][2 * h + 1] - mn) * LOG2E);
                    S[ng][2 * h] = p0;
                    S[ng][2 * h + 1] = p1;
                    rs += p0 + p1;
                }
                rs += __shfl_xor_sync(0xffffffff, rs, 1);
                rs += __shfl_xor_sync(0xffffffff, rs, 2);
                lr[h] = lr[h] * alpha + rs;
                mr[h] = mn;
                #pragma unroll
                for (int ng = 0; ng < 8; ng++) {
                    O[ng][2 * h] *= alpha;
                    O[ng][2 * h + 1] *= alpha;
                }
            }
            #pragma unroll
            for (int ks = 0; ks < 4; ks++) {
                uint32_t Ph[4], Pl[4];
                split2(S[2 * ks][0],     S[2 * ks][1],     Ph[0], Pl[0]);
                split2(S[2 * ks][2],     S[2 * ks][3],     Ph[1], Pl[1]);
                split2(S[2 * ks + 1][0], S[2 * ks + 1][1], Ph[2], Pl[2]);
                split2(S[2 * ks + 1][2], S[2 * ks + 1][3], Ph[3], Pl[3]);
                const int kb = ks * 16 + tig * 2;
                #pragma unroll
                for (int ng = 0; ng < 8; ng++) {
                    const int nr = ng * 8 + gid;
                    uint32_t vh0 = *(const uint32_t*)&sVh[nr * VST + kb];
                    uint32_t vh1 = *(const uint32_t*)&sVh[nr * VST + kb + 8];
                    uint32_t vl0 = *(const uint32_t*)&sVl[nr * VST + kb];
                    uint32_t vl1 = *(const uint32_t*)&sVl[nr * VST + kb + 8];
                    MMA_BF16(O[ng], Ph, vh0, vh1);
                    MMA_BF16(O[ng], Ph, vl0, vl1);
                    MMA_BF16(O[ng], Pl, vh0, vh1);
                }
            }
        }
    }

    const int b = bh >> 4, h = bh & 15;
    #pragma unroll
    for (int hh = 0; hh < 2; hh++) {
        const float inv = 1.f / lr[hh];
        const int q = qA + hh * 8;
        float* og = g_attn + ((size_t)(b * T_ + q)) * D_MODEL + h * DKH;
        #pragma unroll
        for (int ng = 0; ng < 8; ng++) {
            float2 v;
            v.x = O[ng][2 * hh] * inv;
            v.y = O[ng][2 * hh + 1] * inv;
            *(float2*)(og + ng * 8 + tig * 2) = v;
        }
    }
}

// ---------------------------------------------------------------------------
extern "C" void kernel_launch(void* const* d_in, const int* in_sizes, int n_in,
                              void* d_out, int out_size)
{
    const float* x     = (const float*)d_in[0];
    const float* w_qkv = (const float*)d_in[1];
    const float* w_out = (const float*)d_in[2];
    float* out = (float*)d_out;

    static bool attr_set = false;
    if (!attr_set) {
        cudaFuncSetAttribute(attn_mma, cudaFuncAttributeMaxDynamicSharedMemorySize,
                             ATTN_SMEM);
        attr_set = true;
    }

    gemm_mma<0><<<dim3(N_QKV / 128, M_TOT / 128), 256>>>(x, w_qkv, nullptr, N_QKV);
    attn_mma<<<dim3(T_ / 128, B_ * N_HEADS), 256, ATTN_SMEM>>>();
    gemm_mma<1><<<dim3(D_MODEL / 128, M_TOT / 128), 256>>>(nullptr, w_out, out, D_MODEL);
}

// round 17
// speedup vs baseline: 1.3687x; 1.1284x over previous
#include <cuda_runtime.h>
#include <cuda_bf16.h>
#include <cstdint>

#define D_MODEL 1024
#define N_HEADS 16
#define DKH     64
#define B_      4
#define T_      2048
#define M_TOT   (B_ * T_)        // 8192
#define N_QKV   (3 * D_MODEL)    // 3072
#define GK      1024

// ---------------- scratch (device globals; no allocation allowed) ----------
__device__ __nv_bfloat16 g_wqh[(size_t)N_QKV * GK];     // w_qkv^T [N,K] hi
__device__ __nv_bfloat16 g_wql[(size_t)N_QKV * GK];     //               lo
__device__ __nv_bfloat16 g_woh[(size_t)D_MODEL * GK];   // w_out^T [N,K] hi
__device__ __nv_bfloat16 g_wol[(size_t)D_MODEL * GK];   //               lo
__device__ __nv_bfloat16 g_qh[(size_t)64 * T_ * DKH];   // [bh][t][dk], pre-scaled
__device__ __nv_bfloat16 g_ql[(size_t)64 * T_ * DKH];
__device__ __nv_bfloat16 g_kh[(size_t)64 * T_ * DKH];
__device__ __nv_bfloat16 g_kl[(size_t)64 * T_ * DKH];
__device__ __nv_bfloat16 g_vh[(size_t)64 * DKH * T_];   // V^T [bh][dk][t]
__device__ __nv_bfloat16 g_vl[(size_t)64 * DKH * T_];
__device__ float g_attn[(size_t)M_TOT * D_MODEL];

// ============================ helpers ======================================
#define MMA_BF16(D, A, b0, b1) \
    asm volatile("mma.sync.aligned.m16n8k16.row.col.f32.bf16.bf16.f32 " \
        "{%0,%1,%2,%3}, {%4,%5,%6,%7}, {%8,%9}, {%0,%1,%2,%3};" \
        : "+f"((D)[0]), "+f"((D)[1]), "+f"((D)[2]), "+f"((D)[3]) \
        : "r"((A)[0]), "r"((A)[1]), "r"((A)[2]), "r"((A)[3]), "r"(b0), "r"(b1))

#define LDSM_X4(R, a) \
    asm volatile("ldmatrix.sync.aligned.m8n8.x4.shared.b16 {%0,%1,%2,%3}, [%4];" \
        : "=r"((R)[0]), "=r"((R)[1]), "=r"((R)[2]), "=r"((R)[3]) : "r"(a))

__device__ __forceinline__ uint32_t smem_u32(const void* p) {
    uint32_t a;
    asm("{ .reg .u64 t; cvta.to.shared.u64 t, %1; cvt.u32.u64 %0, t; }"
        : "=r"(a) : "l"(p));
    return a;
}
#define CP16(dst, src) \
    asm volatile("cp.async.cg.shared.global [%0], [%1], 16;" \
                 :: "r"((uint32_t)(dst)), "l"(src) : "memory")
#define CP_COMMIT() asm volatile("cp.async.commit_group;" ::: "memory")
#define CP_WAIT0()  asm volatile("cp.async.wait_group 0;" ::: "memory")

__device__ __forceinline__ void bf16_split(float x, unsigned short& h, unsigned short& l)
{
    __nv_bfloat16 hb = __float2bfloat16(x);
    h = __bfloat16_as_ushort(hb);
    l = __bfloat16_as_ushort(__float2bfloat16(x - __bfloat162float(hb)));
}
__device__ __forceinline__ void split2(float a, float b, uint32_t& hi, uint32_t& lo)
{
    unsigned short ha, la, hb, lb;
    bf16_split(a, ha, la);
    bf16_split(b, hb, lb);
    hi = (uint32_t)ha | ((uint32_t)hb << 16);
    lo = (uint32_t)la | ((uint32_t)lb << 16);
}

// ===================== weight transpose+split (runs once, ~25us) ===========
// w fp32 [K,N] -> [N,K] bf16 hi/lo. W=0 -> w_qkv, W=1 -> w_out.
template<int W>
__global__ __launch_bounds__(256)
void cvt_split_T(const float* __restrict__ in, int N)
{
    __shared__ float t[32][33];
    int n0 = blockIdx.x * 32, k0 = blockIdx.y * 32;
    int tx = threadIdx.x, ty = threadIdx.y;   // 32 x 8
    #pragma unroll
    for (int i = 0; i < 4; i++) {
        int k = ty + i * 8;
        t[k][tx] = in[(size_t)(k0 + k) * N + n0 + tx];
    }
    __syncthreads();
    __nv_bfloat16* oh = (W == 0) ? g_wqh : g_woh;
    __nv_bfloat16* ol = (W == 0) ? g_wql : g_wol;
    #pragma unroll
    for (int i = 0; i < 4; i++) {
        int n = ty + i * 8;
        float x = t[tx][n];
        unsigned short hh, ll;
        bf16_split(x, hh, ll);
        size_t o = (size_t)(n0 + n) * GK + k0 + tx;
        oh[o] = __ushort_as_bfloat16(hh);
        ol[o] = __ushort_as_bfloat16(ll);
    }
}

// ===================== double-buffered bf16 HMMA GEMM ======================
// C = AhBh + AhBl + AlBh. CTA 128x128, 8 warps 2x4, warp 64x32, BK=16.
// A (activations) split in-kernel; B (weights) pre-split [N,K] -> uint4 copy.
// Fragments via ldmatrix.x4. Smem stride 24 bf16 = 48 B rows.
#define BKS  16
#define NST  (GK / BKS)
#define AST  24
#define ROWB (AST * 2)            // 48 bytes per row
#define HOFF (128 * ROWB)         // hi->lo array offset 6144 B
#define BUFO (2 * HOFF)           // buffer offset 12288 B

template<int MODE>
__global__ __launch_bounds__(256)
void gemm_mma(const float* __restrict__ Ap, float* __restrict__ Cp, int N)
{
    __shared__ __nv_bfloat16 sA[2][2][128][AST];   // 24 KB
    __shared__ __nv_bfloat16 sB[2][2][128][AST];   // 24 KB

    const int tid  = threadIdx.x;
    const int wid  = tid >> 5;
    const int lane = tid & 31;
    const int wm   = wid & 1;
    const int wn   = wid >> 1;
    const int gid  = lane >> 2;
    const int tig  = lane & 3;
    const int row0 = blockIdx.y * 128;
    const int col0 = blockIdx.x * 128;

    const float* A = (MODE == 1) ? g_attn : Ap;
    const __nv_bfloat16* Bh_g = (MODE == 0) ? g_wqh : g_woh;
    const __nv_bfloat16* Bl_g = (MODE == 0) ? g_wql : g_wol;

    float d[4][4][4];
    #pragma unroll
    for (int i = 0; i < 4; i++)
        #pragma unroll
        for (int j = 0; j < 4; j++)
            #pragma unroll
            for (int e = 0; e < 4; e++) d[i][j][e] = 0.f;

    // A copy slot: rows ar0, ar0+64; 4 fp32 at ac0. B copy slot: row br, 8-bf16 chunk bc.
    const int ar0 = tid >> 2, ac0 = (tid & 3) * 4;
    const int br  = tid >> 1, bc  = (tid & 1) * 8;
    float4 va[2];
    uint4  vbh, vbl;

    // ldmatrix lane addressing (byte offsets within an array)
    const uint32_t uA0 = smem_u32(&sA[0][0][0][0]);
    const uint32_t uB0 = smem_u32(&sB[0][0][0][0]);
    const uint32_t a_lo = (uint32_t)((lane & 15) * ROWB + ((lane >> 4) << 4))
                        + (uint32_t)(wm * 64 * ROWB);
    const uint32_t b_lo = (uint32_t)(((lane >> 4) * 8 + (lane & 7)) * ROWB
                        + (((lane >> 3) & 1) << 4))
                        + (uint32_t)(wn * 32 * ROWB);

    // ---- prologue: load + store stage 0 ----
    #pragma unroll
    for (int i = 0; i < 2; i++)
        va[i] = *(const float4*)(A + (size_t)(row0 + ar0 + i * 64) * GK + ac0);
    vbh = *(const uint4*)(Bh_g + (size_t)(col0 + br) * GK + bc);
    vbl = *(const uint4*)(Bl_g + (size_t)(col0 + br) * GK + bc);

    #pragma unroll
    for (int i = 0; i < 2; i++) {
        const int ra = ar0 + i * 64;
        const float xs[4] = {va[i].x, va[i].y, va[i].z, va[i].w};
        #pragma unroll
        for (int j = 0; j < 2; j++) {
            uint32_t hi, lo;
            split2(xs[2 * j + 0], xs[2 * j + 1], hi, lo);
            *(uint32_t*)&sA[0][0][ra][ac0 + 2 * j] = hi;
            *(uint32_t*)&sA[0][1][ra][ac0 + 2 * j] = lo;
        }
    }
    *(uint4*)&sB[0][0][br][bc] = vbh;
    *(uint4*)&sB[0][1][br][bc] = vbl;
    __syncthreads();

    for (int kt = 0; kt < NST; kt++) {
        const int buf = kt & 1;
        // ---- prefetch stage kt+1 ----
        if (kt + 1 < NST) {
            const int k0 = (kt + 1) * BKS;
            #pragma unroll
            for (int i = 0; i < 2; i++)
                va[i] = *(const float4*)(A + (size_t)(row0 + ar0 + i * 64) * GK + k0 + ac0);
            vbh = *(const uint4*)(Bh_g + (size_t)(col0 + br) * GK + k0 + bc);
            vbl = *(const uint4*)(Bl_g + (size_t)(col0 + br) * GK + k0 + bc);
        }

        // ---- fragment loads via ldmatrix ----
        const uint32_t aBase = uA0 + buf * BUFO + a_lo;
        const uint32_t bBase = uB0 + buf * BUFO + b_lo;
        uint32_t Ah[4][4], Al[4][4];
        #pragma unroll
        for (int mi = 0; mi < 4; mi++) {
            LDSM_X4(Ah[mi], aBase + mi * (16 * ROWB));
            LDSM_X4(Al[mi], aBase + mi * (16 * ROWB) + HOFF);
        }
        uint32_t Bh[4][2], Bl[4][2];
        #pragma unroll
        for (int p = 0; p < 2; p++) {
            uint32_t rh[4], rl[4];
            LDSM_X4(rh, bBase + p * (16 * ROWB));
            LDSM_X4(rl, bBase + p * (16 * ROWB) + HOFF);
            Bh[2 * p][0] = rh[0]; Bh[2 * p][1] = rh[1];
            Bh[2 * p + 1][0] = rh[2]; Bh[2 * p + 1][1] = rh[3];
            Bl[2 * p][0] = rl[0]; Bl[2 * p][1] = rl[1];
            Bl[2 * p + 1][0] = rl[2]; Bl[2 * p + 1][1] = rl[3];
        }
        #pragma unroll
        for (int mi = 0; mi < 4; mi++)
            #pragma unroll
            for (int ng = 0; ng < 4; ng++) {
                MMA_BF16(d[mi][ng], Ah[mi], Bh[ng][0], Bh[ng][1]);
                MMA_BF16(d[mi][ng], Ah[mi], Bl[ng][0], Bl[ng][1]);
                MMA_BF16(d[mi][ng], Al[mi], Bh[ng][0], Bh[ng][1]);
            }

        // ---- store stage kt+1 ----
        if (kt + 1 < NST) {
            const int nb = buf ^ 1;
            #pragma unroll
            for (int i = 0; i < 2; i++) {
                const int ra = ar0 + i * 64;
                const float xs[4] = {va[i].x, va[i].y, va[i].z, va[i].w};
                #pragma unroll
                for (int j = 0; j < 2; j++) {
                    uint32_t hi, lo;
                    split2(xs[2 * j + 0], xs[2 * j + 1], hi, lo);
                    *(uint32_t*)&sA[nb][0][ra][ac0 + 2 * j] = hi;
                    *(uint32_t*)&sA[nb][1][ra][ac0 + 2 * j] = lo;
                }
            }
            *(uint4*)&sB[nb][0][br][bc] = vbh;
            *(uint4*)&sB[nb][1][br][bc] = vbl;
        }
        __syncthreads();
    }

    // ---------------- epilogue ----------------
    #pragma unroll
    for (int mi = 0; mi < 4; mi++)
        #pragma unroll
        for (int ng = 0; ng < 4; ng++) {
            const int n = col0 + wn * 32 + ng * 8 + tig * 2;
            #pragma unroll
            for (int h = 0; h < 2; h++) {
                const int m = row0 + wm * 64 + mi * 16 + gid + h * 8;
                float2 v;
                v.x = d[mi][ng][h * 2 + 0];
                v.y = d[mi][ng][h * 2 + 1];
                if (MODE == 0) {
                    const int b = m >> 11, t = m & (T_ - 1);
                    const int sidx = n >> 10;
                    const int dmi  = n & (D_MODEL - 1);
                    const int hh = dmi >> 6, dk = dmi & (DKH - 1);
                    const int bh = (b << 4) + hh;
                    if (sidx == 0) {
                        uint32_t hi, lo;
                        split2(0.125f * v.x, 0.125f * v.y, hi, lo);
                        const size_t idx = ((size_t)bh * T_ + t) * DKH + dk;
                        *(uint32_t*)&g_qh[idx] = hi;
                        *(uint32_t*)&g_ql[idx] = lo;
                    } else if (sidx == 1) {
                        uint32_t hi, lo;
                        split2(v.x, v.y, hi, lo);
                        const size_t idx = ((size_t)bh * T_ + t) * DKH + dk;
                        *(uint32_t*)&g_kh[idx] = hi;
                        *(uint32_t*)&g_kl[idx] = lo;
                    } else {
                        unsigned short h0, l0, h1, l1;
                        bf16_split(v.x, h0, l0);
                        bf16_split(v.y, h1, l1);
                        const size_t i0 = ((size_t)bh * DKH + dk) * T_ + t;
                        g_vh[i0] = __ushort_as_bfloat16(h0);
                        g_vl[i0] = __ushort_as_bfloat16(l0);
                        g_vh[i0 + T_] = __ushort_as_bfloat16(h1);
                        g_vl[i0 + T_] = __ushort_as_bfloat16(l1);
                    }
                } else {
                    *(float2*)(Cp + (size_t)m * N + n) = v;
                }
            }
        }
}

// ===================== bf16 HMMA causal flash attention (R15/16, proven) ===
#define VST 72
#define ATILE  (64 * VST * 2)     // 9216 B per array
#define ASTAGE (4 * ATILE)        // 36864 B per stage
#define ATTN_SMEM (2 * ASTAGE)    // 73728 B

__global__ __launch_bounds__(256, 2)
void attn_mma()
{
    extern __shared__ __align__(16) char smem[];

    const int bh  = blockIdx.y;
    const int q0  = blockIdx.x * 128;
    const int tid = threadIdx.x;
    const int wid = tid >> 5;
    const int lane = tid & 31;
    const int gid = lane >> 2;
    const int tig = lane & 3;

    const __nv_bfloat16* Qh_g = g_qh + ((size_t)bh * T_ + q0) * DKH;
    const __nv_bfloat16* Ql_g = g_ql + ((size_t)bh * T_ + q0) * DKH;
    const __nv_bfloat16* Kh_g = g_kh + (size_t)bh * T_ * DKH;
    const __nv_bfloat16* Kl_g = g_kl + (size_t)bh * T_ * DKH;
    const __nv_bfloat16* Vh_g = g_vh + (size_t)bh * DKH * T_;
    const __nv_bfloat16* Vl_g = g_vl + (size_t)bh * DKH * T_;
    const float LOG2E = 1.4426950408889634f;
    const uint32_t sb = smem_u32(smem);

    // ---- Q fragments (staged through stage-0 K arrays, two 64-row passes) --
    uint32_t Qh[4][4], Ql[4][4];
    {
        __nv_bfloat16* tKh = (__nv_bfloat16*)(smem);
        __nv_bfloat16* tKl = (__nv_bfloat16*)(smem + ATILE);
        #pragma unroll
        for (int pass = 0; pass < 2; pass++) {
            #pragma unroll
            for (int i = 0; i < 2; i++) {
                const int c = tid + i * 256;
                const int rr = c >> 3, cc = (c & 7) * 8;
                *(uint4*)&tKh[rr * VST + cc] =
                    *(const uint4*)(Qh_g + (size_t)(pass * 64 + rr) * DKH + cc);
                *(uint4*)&tKl[rr * VST + cc] =
                    *(const uint4*)(Ql_g + (size_t)(pass * 64 + rr) * DKH + cc);
            }
            __syncthreads();
            if ((wid >> 2) == pass) {
                const int rb = (wid & 3) * 16 + gid;
                #pragma unroll
                for (int ks = 0; ks < 4; ks++) {
                    const int kb = ks * 16 + tig * 2;
                    Qh[ks][0] = *(const uint32_t*)&tKh[rb * VST + kb];
                    Qh[ks][1] = *(const uint32_t*)&tKh[(rb + 8) * VST + kb];
                    Qh[ks][2] = *(const uint32_t*)&tKh[rb * VST + kb + 8];
                    Qh[ks][3] = *(const uint32_t*)&tKh[(rb + 8) * VST + kb + 8];
                    Ql[ks][0] = *(const uint32_t*)&tKl[rb * VST + kb];
                    Ql[ks][1] = *(const uint32_t*)&tKl[(rb + 8) * VST + kb];
                    Ql[ks][2] = *(const uint32_t*)&tKl[rb * VST + kb + 8];
                    Ql[ks][3] = *(const uint32_t*)&tKl[(rb + 8) * VST + kb + 8];
                }
            }
            __syncthreads();
        }
    }

    float O[8][4];
    #pragma unroll
    for (int i = 0; i < 8; i++)
        #pragma unroll
        for (int e = 0; e < 4; e++) O[i][e] = 0.f;
    float mr[2] = {-1e30f, -1e30f}, lr[2] = {0.f, 0.f};

    const int qA = q0 + wid * 16 + gid;
    const int ntiles = (q0 >> 6) + 2;

    auto issue = [&](int t, int s) {
        const int k0 = t * 64;
        const uint32_t base = sb + (uint32_t)s * ASTAGE;
        #pragma unroll
        for (int i = 0; i < 2; i++) {
            const int c = tid + i * 256;
            const int rr = c >> 3, cc = (c & 7) * 8;
            const uint32_t ro = (uint32_t)(rr * VST + cc) * 2;
            CP16(base + 0 * ATILE + ro, Kh_g + (size_t)(k0 + rr) * DKH + cc);
            CP16(base + 1 * ATILE + ro, Kl_g + (size_t)(k0 + rr) * DKH + cc);
            CP16(base + 2 * ATILE + ro, Vh_g + (size_t)rr * T_ + k0 + cc);
            CP16(base + 3 * ATILE + ro, Vl_g + (size_t)rr * T_ + k0 + cc);
        }
        CP_COMMIT();
    };

    issue(0, 0);

    for (int t = 0; t < ntiles; t++) {
        const int k0 = t * 64;
        CP_WAIT0();
        __syncthreads();
        if (t + 1 < ntiles) issue(t + 1, (t + 1) & 1);

        if (k0 <= q0 + wid * 16 + 15) {
            const char* stg = smem + (t & 1) * ASTAGE;
            const __nv_bfloat16* sKh = (const __nv_bfloat16*)(stg);
            const __nv_bfloat16* sKl = (const __nv_bfloat16*)(stg + ATILE);
            const __nv_bfloat16* sVh = (const __nv_bfloat16*)(stg + 2 * ATILE);
            const __nv_bfloat16* sVl = (const __nv_bfloat16*)(stg + 3 * ATILE);

            float S[8][4];
            #pragma unroll
            for (int i = 0; i < 8; i++)
                #pragma unroll
                for (int e = 0; e < 4; e++) S[i][e] = 0.f;
            #pragma unroll
            for (int ks = 0; ks < 4; ks++) {
                const int kb = ks * 16 + tig * 2;
                #pragma unroll
                for (int ng = 0; ng < 8; ng++) {
                    const int nr = ng * 8 + gid;
                    uint32_t bh0 = *(const uint32_t*)&sKh[nr * VST + kb];
                    uint32_t bh1 = *(const uint32_t*)&sKh[nr * VST + kb + 8];
                    uint32_t bl0 = *(const uint32_t*)&sKl[nr * VST + kb];
                    uint32_t bl1 = *(const uint32_t*)&sKl[nr * VST + kb + 8];
                    MMA_BF16(S[ng], Qh[ks], bh0, bh1);
                    MMA_BF16(S[ng], Qh[ks], bl0, bl1);
                    MMA_BF16(S[ng], Ql[ks], bh0, bh1);
                }
            }
            if (k0 + 63 > q0 + wid * 16) {
                #pragma unroll
                for (int ng = 0; ng < 8; ng++)
                    #pragma unroll
                    for (int e = 0; e < 4; e++) {
                        const int key = k0 + ng * 8 + tig * 2 + (e & 1);
                        const int q   = qA + (e >> 1) * 8;
                        if (key > q) S[ng][e] = -1e30f;
                    }
            }
            #pragma unroll
            for (int h = 0; h < 2; h++) {
                float mt = -1e30f;
                #pragma unroll
                for (int ng = 0; ng < 8; ng++)
                    mt = fmaxf(mt, fmaxf(S[ng][2 * h], S[ng][2 * h + 1]));
                mt = fmaxf(mt, __shfl_xor_sync(0xffffffff, mt, 1));
                mt = fmaxf(mt, __shfl_xor_sync(0xffffffff, mt, 2));
                const float mn = fmaxf(mr[h], mt);
                const float alpha = exp2f((mr[h] - mn) * LOG2E);
                float rs = 0.f;
                #pragma unroll
                for (int ng = 0; ng < 8; ng++) {
                    float p0 = exp2f((S[ng][2 * h] - mn) * LOG2E);
                    float p1 = exp2f((S[ng][2 * h + 1] - mn) * LOG2E);
                    S[ng][2 * h] = p0;
                    S[ng][2 * h + 1] = p1;
                    rs += p0 + p1;
                }
                rs += __shfl_xor_sync(0xffffffff, rs, 1);
                rs += __shfl_xor_sync(0xffffffff, rs, 2);
                lr[h] = lr[h] * alpha + rs;
                mr[h] = mn;
                #pragma unroll
                for (int ng = 0; ng < 8; ng++) {
                    O[ng][2 * h] *= alpha;
                    O[ng][2 * h + 1] *= alpha;
                }
            }
            #pragma unroll
            for (int ks = 0; ks < 4; ks++) {
                uint32_t Ph[4], Pl[4];
                split2(S[2 * ks][0],     S[2 * ks][1],     Ph[0], Pl[0]);
                split2(S[2 * ks][2],     S[2 * ks][3],     Ph[1], Pl[1]);
                split2(S[2 * ks + 1][0], S[2 * ks + 1][1], Ph[2], Pl[2]);
                split2(S[2 * ks + 1][2], S[2 * ks + 1][3], Ph[3], Pl[3]);
                const int kb = ks * 16 + tig * 2;
                #pragma unroll
                for (int ng = 0; ng < 8; ng++) {
                    const int nr = ng * 8 + gid;
                    uint32_t vh0 = *(const uint32_t*)&sVh[nr * VST + kb];
                    uint32_t vh1 = *(const uint32_t*)&sVh[nr * VST + kb + 8];
                    uint32_t vl0 = *(const uint32_t*)&sVl[nr * VST + kb];
                    uint32_t vl1 = *(const uint32_t*)&sVl[nr * VST + kb + 8];
                    MMA_BF16(O[ng], Ph, vh0, vh1);
                    MMA_BF16(O[ng], Ph, vl0, vl1);
                    MMA_BF16(O[ng], Pl, vh0, vh1);
                }
            }
        }
    }

    const int b = bh >> 4, h = bh & 15;
    #pragma unroll
    for (int hh = 0; hh < 2; hh++) {
        const float inv = 1.f / lr[hh];
        const int q = qA + hh * 8;
        float* og = g_attn + ((size_t)(b * T_ + q)) * D_MODEL + h * DKH;
        #pragma unroll
        for (int ng = 0; ng < 8; ng++) {
            float2 v;
            v.x = O[ng][2 * hh] * inv;
            v.y = O[ng][2 * hh + 1] * inv;
            *(float2*)(og + ng * 8 + tig * 2) = v;
        }
    }
}

// ---------------------------------------------------------------------------
extern "C" void kernel_launch(void* const* d_in, const int* in_sizes, int n_in,
                              void* d_out, int out_size)
{
    const float* x     = (const float*)d_in[0];
    const float* w_qkv = (const float*)d_in[1];
    const float* w_out = (const float*)d_in[2];
    float* out = (float*)d_out;

    static bool attr_set = false;
    if (!attr_set) {
        cudaFuncSetAttribute(attn_mma, cudaFuncAttributeMaxDynamicSharedMemorySize,
                             ATTN_SMEM);
        attr_set = true;
    }

    // pre-split weights once (globals referenced inside kernels)
    cvt_split_T<0><<<dim3(N_QKV / 32, GK / 32), dim3(32, 8)>>>(w_qkv, N_QKV);
    cvt_split_T<1><<<dim3(D_MODEL / 32, GK / 32), dim3(32, 8)>>>(w_out, D_MODEL);

    gemm_mma<0><<<dim3(N_QKV / 128, M_TOT / 128), 256>>>(x, nullptr, N_QKV);
    attn_mma<<<dim3(T_ / 128, B_ * N_HEADS), 256, ATTN_SMEM>>>();
    gemm_mma<1><<<dim3(D_MODEL / 128, M_TOT / 128), 256>>>(nullptr, out, D_MODEL);
}